// round 15
// baseline (speedup 1.0000x reference)
#include <cuda_runtime.h>
#include <cuda_bf16.h>
#include <mma.h>
#include <cstdint>

using namespace nvcuda;

#define N_NODES 100000
#define N_EDGES 1600000
#define SZ_IN   128
#define DIM_I   1024

#define KC  32      // K chunk for kernel 1 (static smem)
#define LDP 40      // padded smem ld; stride%32==8 (R4-validated bank pattern)
#define LDC 132     // padded staging ld for kernel-1 epilogue

#define KC2  64     // K chunk for output GEMM (dynamic smem)
#define LDP2 72     // 64+8; stride%32==8, same bank pattern class as 40

// Scratch: node-transformed features y = relu(x @ W^T + b), and scatter-max result hn.
__device__ float g_y[N_NODES * SZ_IN];   // 51.2 MB
__device__ float g_hn[N_NODES * SZ_IN];  // 51.2 MB

__device__ __forceinline__ float4 to_tf32x4(float4 v) {
    v.x = wmma::__float_to_tf32(v.x);
    v.y = wmma::__float_to_tf32(v.y);
    v.z = wmma::__float_to_tf32(v.z);
    v.w = wmma::__float_to_tf32(v.w);
    return v;
}

// ---------------------------------------------------------------------------
// Kernel 1: y = relu(x @ agg_W^T + agg_b)   [100000 x 128], K=128 (unchanged)
// ---------------------------------------------------------------------------
__global__ void __launch_bounds__(256) node_transform_kernel(
    const float* __restrict__ x,
    const float* __restrict__ W,
    const float* __restrict__ bias)
{
    __shared__ float As[128 * LDP];
    __shared__ float Bs[128 * LDP];
    __shared__ float Cs[128 * LDC];

    const int tid  = threadIdx.x;
    const int warp = tid >> 5;
    const int m0   = blockIdx.x * 128;
    const int wm   = warp >> 2;
    const int wn   = warp & 3;

    wmma::fragment<wmma::accumulator, 16, 16, 8, float> acc[4][2];
#pragma unroll
    for (int i = 0; i < 4; i++)
#pragma unroll
        for (int j = 0; j < 2; j++) wmma::fill_fragment(acc[i][j], 0.0f);

    for (int kc = 0; kc < SZ_IN; kc += KC) {
#pragma unroll
        for (int it = 0; it < 4; it++) {
            const int idx = it * 256 + tid;
            const int r  = idx >> 3;
            const int kq = idx & 7;
            const int row = m0 + r;
            float4 a = make_float4(0.f, 0.f, 0.f, 0.f);
            if (row < N_NODES)
                a = *reinterpret_cast<const float4*>(x + (size_t)row * SZ_IN + kc + kq * 4);
            *reinterpret_cast<float4*>(&As[r * LDP + kq * 4]) = to_tf32x4(a);
            float4 b = *reinterpret_cast<const float4*>(W + (size_t)r * SZ_IN + kc + kq * 4);
            *reinterpret_cast<float4*>(&Bs[r * LDP + kq * 4]) = to_tf32x4(b);
        }
        __syncthreads();
#pragma unroll
        for (int ks = 0; ks < KC / 8; ks++) {
            wmma::fragment<wmma::matrix_a, 16, 16, 8, wmma::precision::tf32, wmma::row_major> a[4];
#pragma unroll
            for (int i = 0; i < 4; i++)
                wmma::load_matrix_sync(a[i], &As[(wm * 64 + i * 16) * LDP + ks * 8], LDP);
            wmma::fragment<wmma::matrix_b, 16, 16, 8, wmma::precision::tf32, wmma::col_major> b[2];
#pragma unroll
            for (int j = 0; j < 2; j++)
                wmma::load_matrix_sync(b[j], &Bs[(wn * 32 + j * 16) * LDP + ks * 8], LDP);
#pragma unroll
            for (int i = 0; i < 4; i++)
#pragma unroll
                for (int j = 0; j < 2; j++)
                    wmma::mma_sync(acc[i][j], a[i], b[j], acc[i][j]);
        }
        __syncthreads();
    }

#pragma unroll
    for (int i = 0; i < 4; i++)
#pragma unroll
        for (int j = 0; j < 2; j++)
            wmma::store_matrix_sync(&Cs[(wm * 64 + i * 16) * LDC + wn * 32 + j * 16],
                                    acc[i][j], LDC, wmma::mem_row_major);
    __syncthreads();
    for (int idx = tid; idx < 128 * SZ_IN; idx += 256) {
        const int r   = idx >> 7;
        const int c   = idx & 127;
        const int row = m0 + r;
        if (row < N_NODES) {
            float v = Cs[r * LDC + c] + bias[c];
            g_y[(size_t)row * SZ_IN + c] = v > 0.0f ? v : 0.0f;
        }
    }
}

// ---------------------------------------------------------------------------
// Kernel 2: zero hn
// ---------------------------------------------------------------------------
__global__ void __launch_bounds__(256) zero_hn_kernel() {
    const size_t total4 = (size_t)N_NODES * SZ_IN / 4;
    float4 z = make_float4(0.f, 0.f, 0.f, 0.f);
    for (size_t i = (size_t)blockIdx.x * blockDim.x + threadIdx.x; i < total4;
         i += (size_t)gridDim.x * blockDim.x)
        reinterpret_cast<float4*>(g_hn)[i] = z;
}

// ---------------------------------------------------------------------------
// Kernel 3: scatter-max (unchanged)
// ---------------------------------------------------------------------------
__global__ void __launch_bounds__(256) scatter_max_kernel(
    const int* __restrict__ edge_index, int num_edges)
{
    const int e = (blockIdx.x * blockDim.x + threadIdx.x) >> 5;
    const int lane = threadIdx.x & 31;
    if (e >= num_edges) return;
    const int u = edge_index[e];
    const int v = edge_index[num_edges + e];
    if ((unsigned)u >= N_NODES || (unsigned)v >= N_NODES) return;
    const float* src = g_y + (size_t)v * SZ_IN;
    int* dst = reinterpret_cast<int*>(g_hn + (size_t)u * SZ_IN);
#pragma unroll
    for (int j = 0; j < 4; j++) {
        const int f = lane + 32 * j;
        const float val = __ldg(&src[f]);
        if (val > 0.0f) atomicMax(&dst[f], __float_as_int(val));
    }
}

// ---------------------------------------------------------------------------
// Kernel 4: h = relu(concat(x, hn) @ lin_W^T)   [100000 x 1024], K=256.
// KC2=64: 4 stage/sync rounds instead of 8 -> half the barriers, 2x the LDG
// MLP per exposed-latency window, 8-step unrolled MMA runs between barriers.
// Dynamic smem 72KB/CTA (2 CTAs/SM at 144KB). Grid (n=8 fast, m=782) keeps
// the validated L2 A-reuse (DRAM ~8%).
// ---------------------------------------------------------------------------
#define GSMEM_BYTES (2 * 128 * LDP2 * 4)   // 73728

__global__ void __launch_bounds__(256) output_gemm_kernel(
    const float* __restrict__ x,
    const float* __restrict__ lw,    // [1024, 256] row-major (out,in)
    float* __restrict__ out)
{
    extern __shared__ float smem[];
    float* As = smem;                 // 128 x LDP2
    float* Bs = smem + 128 * LDP2;    // 128 x LDP2

    const int tid  = threadIdx.x;
    const int warp = tid >> 5;
    const int n0   = blockIdx.x * 128;   // 8 n-tiles, fast dimension
    const int m0   = blockIdx.y * 128;   // 782 m-tiles
    const int wm   = warp >> 2;   // 0..1
    const int wn   = warp & 3;    // 0..3

    wmma::fragment<wmma::accumulator, 16, 16, 8, float> acc[4][2];
#pragma unroll
    for (int i = 0; i < 4; i++)
#pragma unroll
        for (int j = 0; j < 2; j++) wmma::fill_fragment(acc[i][j], 0.0f);

    for (int kc = 0; kc < 2 * SZ_IN; kc += KC2) {
        const float* Abase = (kc < SZ_IN) ? (x + kc) : (g_hn + (kc - SZ_IN));
        // stage A[128m x 64k] and B[128n x 64k]: 2048 float4 each, 8 per thread
#pragma unroll
        for (int it = 0; it < 8; it++) {
            const int idx = it * 256 + tid;   // 0..2047
            const int r  = idx >> 4;          // 0..127
            const int kq = idx & 15;          // float4 index along 64 k
            const int row = m0 + r;
            float4 a = make_float4(0.f, 0.f, 0.f, 0.f);
            if (row < N_NODES)
                a = *reinterpret_cast<const float4*>(Abase + (size_t)row * SZ_IN + kq * 4);
            *reinterpret_cast<float4*>(&As[r * LDP2 + kq * 4]) = to_tf32x4(a);
            float4 b = *reinterpret_cast<const float4*>(
                lw + (size_t)(n0 + r) * 256 + kc + kq * 4);
            *reinterpret_cast<float4*>(&Bs[r * LDP2 + kq * 4]) = to_tf32x4(b);
        }
        __syncthreads();
#pragma unroll
        for (int ks = 0; ks < KC2 / 8; ks++) {
            wmma::fragment<wmma::matrix_a, 16, 16, 8, wmma::precision::tf32, wmma::row_major> a[4];
#pragma unroll
            for (int i = 0; i < 4; i++)
                wmma::load_matrix_sync(a[i], &As[(wm * 64 + i * 16) * LDP2 + ks * 8], LDP2);
            wmma::fragment<wmma::matrix_b, 16, 16, 8, wmma::precision::tf32, wmma::col_major> b[2];
#pragma unroll
            for (int j = 0; j < 2; j++)
                wmma::load_matrix_sync(b[j], &Bs[(wn * 32 + j * 16) * LDP2 + ks * 8], LDP2);
#pragma unroll
            for (int i = 0; i < 4; i++)
#pragma unroll
                for (int j = 0; j < 2; j++)
                    wmma::mma_sync(acc[i][j], a[i], b[j], acc[i][j]);
        }
        __syncthreads();
    }

    // epilogue: relu + direct wmma store (16-row tiles all-valid or all-OOB)
#pragma unroll
    for (int i = 0; i < 4; i++) {
        const int mrow = m0 + wm * 64 + i * 16;
        if (mrow + 16 > N_NODES) continue;
#pragma unroll
        for (int j = 0; j < 2; j++) {
#pragma unroll
            for (int e = 0; e < acc[i][j].num_elements; e++)
                acc[i][j].x[e] = fmaxf(acc[i][j].x[e], 0.0f);
            wmma::store_matrix_sync(out + (size_t)mrow * DIM_I + n0 + wn * 32 + j * 16,
                                    acc[i][j], DIM_I, wmma::mem_row_major);
        }
    }
}

// ---------------------------------------------------------------------------
extern "C" void kernel_launch(void* const* d_in, const int* in_sizes, int n_in,
                              void* d_out, int out_size) {
    const float* x     = (const float*)d_in[0];
    const int*   eidx  = (const int*)d_in[1];      // int32 (JAX x64 disabled)
    const float* agg_W = (const float*)d_in[2];
    const float* agg_b = (const float*)d_in[3];
    const float* lin_W = (const float*)d_in[4];
    float*       out   = (float*)d_out;

    const int num_edges = in_sizes[1] / 2;
    const int m_blocks = (N_NODES + 127) / 128;         // 782

    cudaFuncSetAttribute(output_gemm_kernel,
                         cudaFuncAttributeMaxDynamicSharedMemorySize, GSMEM_BYTES);

    // 1) per-node transform
    node_transform_kernel<<<m_blocks, 256>>>(x, agg_W, agg_b);
    // 2) zero hn
    zero_hn_kernel<<<6400, 256>>>();
    // 3) scatter-max over edges
    {
        const long long total_threads = (long long)num_edges * 32;
        const int blocks = (int)((total_threads + 255) / 256); // 200000
        scatter_max_kernel<<<blocks, 256>>>(eidx, num_edges);
    }
    // 4) output GEMM + relu  (n-tiles fast; KC2=64 staging)
    {
        dim3 grid(DIM_I / 128, m_blocks);               // (8, 782)
        output_gemm_kernel<<<grid, 256, GSMEM_BYTES>>>(x, lin_W, out);
    }
}

// round 17
// speedup vs baseline: 1.2716x; 1.2716x over previous
#include <cuda_runtime.h>
#include <cuda_bf16.h>
#include <mma.h>
#include <cstdint>

using namespace nvcuda;

#define N_NODES 100000
#define N_EDGES 1600000
#define SZ_IN   128
#define DIM_I   1024

#define KC  32      // K chunk for kernel 1 (static smem)
#define LDP 40      // padded smem ld; stride%32==8 (R4-validated bank pattern)
#define LDC 132     // padded staging ld for kernel-1 epilogue

#define KC2  64     // K chunk for output GEMM (dynamic smem)
#define LDP2 72     // 64+8; stride%32==8, same bank pattern class as 40

// Scratch: node-transformed features y = relu(x @ W^T + b), and scatter-max result hn.
__device__ float g_y[N_NODES * SZ_IN];   // 51.2 MB
__device__ float g_hn[N_NODES * SZ_IN];  // 51.2 MB

__device__ __forceinline__ float4 to_tf32x4(float4 v) {
    v.x = wmma::__float_to_tf32(v.x);
    v.y = wmma::__float_to_tf32(v.y);
    v.z = wmma::__float_to_tf32(v.z);
    v.w = wmma::__float_to_tf32(v.w);
    return v;
}

// ---------------------------------------------------------------------------
// Kernel 1: y = relu(x @ agg_W^T + agg_b)   [100000 x 128], K=128 (unchanged)
// ---------------------------------------------------------------------------
__global__ void __launch_bounds__(256) node_transform_kernel(
    const float* __restrict__ x,
    const float* __restrict__ W,
    const float* __restrict__ bias)
{
    __shared__ float As[128 * LDP];
    __shared__ float Bs[128 * LDP];
    __shared__ float Cs[128 * LDC];

    const int tid  = threadIdx.x;
    const int warp = tid >> 5;
    const int m0   = blockIdx.x * 128;
    const int wm   = warp >> 2;
    const int wn   = warp & 3;

    wmma::fragment<wmma::accumulator, 16, 16, 8, float> acc[4][2];
#pragma unroll
    for (int i = 0; i < 4; i++)
#pragma unroll
        for (int j = 0; j < 2; j++) wmma::fill_fragment(acc[i][j], 0.0f);

    for (int kc = 0; kc < SZ_IN; kc += KC) {
#pragma unroll
        for (int it = 0; it < 4; it++) {
            const int idx = it * 256 + tid;
            const int r  = idx >> 3;
            const int kq = idx & 7;
            const int row = m0 + r;
            float4 a = make_float4(0.f, 0.f, 0.f, 0.f);
            if (row < N_NODES)
                a = *reinterpret_cast<const float4*>(x + (size_t)row * SZ_IN + kc + kq * 4);
            *reinterpret_cast<float4*>(&As[r * LDP + kq * 4]) = to_tf32x4(a);
            float4 b = *reinterpret_cast<const float4*>(W + (size_t)r * SZ_IN + kc + kq * 4);
            *reinterpret_cast<float4*>(&Bs[r * LDP + kq * 4]) = to_tf32x4(b);
        }
        __syncthreads();
#pragma unroll
        for (int ks = 0; ks < KC / 8; ks++) {
            wmma::fragment<wmma::matrix_a, 16, 16, 8, wmma::precision::tf32, wmma::row_major> a[4];
#pragma unroll
            for (int i = 0; i < 4; i++)
                wmma::load_matrix_sync(a[i], &As[(wm * 64 + i * 16) * LDP + ks * 8], LDP);
            wmma::fragment<wmma::matrix_b, 16, 16, 8, wmma::precision::tf32, wmma::col_major> b[2];
#pragma unroll
            for (int j = 0; j < 2; j++)
                wmma::load_matrix_sync(b[j], &Bs[(wn * 32 + j * 16) * LDP + ks * 8], LDP);
#pragma unroll
            for (int i = 0; i < 4; i++)
#pragma unroll
                for (int j = 0; j < 2; j++)
                    wmma::mma_sync(acc[i][j], a[i], b[j], acc[i][j]);
        }
        __syncthreads();
    }

#pragma unroll
    for (int i = 0; i < 4; i++)
#pragma unroll
        for (int j = 0; j < 2; j++)
            wmma::store_matrix_sync(&Cs[(wm * 64 + i * 16) * LDC + wn * 32 + j * 16],
                                    acc[i][j], LDC, wmma::mem_row_major);
    __syncthreads();
    for (int idx = tid; idx < 128 * SZ_IN; idx += 256) {
        const int r   = idx >> 7;
        const int c   = idx & 127;
        const int row = m0 + r;
        if (row < N_NODES) {
            float v = Cs[r * LDC + c] + bias[c];
            g_y[(size_t)row * SZ_IN + c] = v > 0.0f ? v : 0.0f;
        }
    }
}

// ---------------------------------------------------------------------------
// Kernel 2: zero hn
// ---------------------------------------------------------------------------
__global__ void __launch_bounds__(256) zero_hn_kernel() {
    const size_t total4 = (size_t)N_NODES * SZ_IN / 4;
    float4 z = make_float4(0.f, 0.f, 0.f, 0.f);
    for (size_t i = (size_t)blockIdx.x * blockDim.x + threadIdx.x; i < total4;
         i += (size_t)gridDim.x * blockDim.x)
        reinterpret_cast<float4*>(g_hn)[i] = z;
}

// ---------------------------------------------------------------------------
// Kernel 3: scatter-max (unchanged)
// ---------------------------------------------------------------------------
__global__ void __launch_bounds__(256) scatter_max_kernel(
    const int* __restrict__ edge_index, int num_edges)
{
    const int e = (blockIdx.x * blockDim.x + threadIdx.x) >> 5;
    const int lane = threadIdx.x & 31;
    if (e >= num_edges) return;
    const int u = edge_index[e];
    const int v = edge_index[num_edges + e];
    if ((unsigned)u >= N_NODES || (unsigned)v >= N_NODES) return;
    const float* src = g_y + (size_t)v * SZ_IN;
    int* dst = reinterpret_cast<int*>(g_hn + (size_t)u * SZ_IN);
#pragma unroll
    for (int j = 0; j < 4; j++) {
        const int f = lane + 32 * j;
        const float val = __ldg(&src[f]);
        if (val > 0.0f) atomicMax(&dst[f], __float_as_int(val));
    }
}

// ---------------------------------------------------------------------------
// Kernel 4: h = relu(concat(x, hn) @ lin_W^T)   [100000 x 1024], K=256.
// KC2=64 (4 stage/sync rounds) WITH __launch_bounds__(256, 2): caps regs at
// 128 so 2 CTAs/SM are resident again (R15's 142 regs dropped to 1 CTA and
// regressed). ~14 spilled regs land in the staging loop, covered by the
// co-resident CTA. Grid (n=8 fast, m=782) keeps the validated L2 A-reuse.
// ---------------------------------------------------------------------------
#define GSMEM_BYTES (2 * 128 * LDP2 * 4)   // 73728

__global__ void __launch_bounds__(256, 2) output_gemm_kernel(
    const float* __restrict__ x,
    const float* __restrict__ lw,    // [1024, 256] row-major (out,in)
    float* __restrict__ out)
{
    extern __shared__ float smem[];
    float* As = smem;                 // 128 x LDP2
    float* Bs = smem + 128 * LDP2;    // 128 x LDP2

    const int tid  = threadIdx.x;
    const int warp = tid >> 5;
    const int n0   = blockIdx.x * 128;   // 8 n-tiles, fast dimension
    const int m0   = blockIdx.y * 128;   // 782 m-tiles
    const int wm   = warp >> 2;   // 0..1
    const int wn   = warp & 3;    // 0..3

    wmma::fragment<wmma::accumulator, 16, 16, 8, float> acc[4][2];
#pragma unroll
    for (int i = 0; i < 4; i++)
#pragma unroll
        for (int j = 0; j < 2; j++) wmma::fill_fragment(acc[i][j], 0.0f);

    for (int kc = 0; kc < 2 * SZ_IN; kc += KC2) {
        const float* Abase = (kc < SZ_IN) ? (x + kc) : (g_hn + (kc - SZ_IN));
        // stage A[128m x 64k] and B[128n x 64k]: 2048 float4 each, 8 per thread
#pragma unroll
        for (int it = 0; it < 8; it++) {
            const int idx = it * 256 + tid;   // 0..2047
            const int r  = idx >> 4;          // 0..127
            const int kq = idx & 15;          // float4 index along 64 k
            const int row = m0 + r;
            float4 a = make_float4(0.f, 0.f, 0.f, 0.f);
            if (row < N_NODES)
                a = *reinterpret_cast<const float4*>(Abase + (size_t)row * SZ_IN + kq * 4);
            *reinterpret_cast<float4*>(&As[r * LDP2 + kq * 4]) = to_tf32x4(a);
            float4 b = *reinterpret_cast<const float4*>(
                lw + (size_t)(n0 + r) * 256 + kc + kq * 4);
            *reinterpret_cast<float4*>(&Bs[r * LDP2 + kq * 4]) = to_tf32x4(b);
        }
        __syncthreads();
#pragma unroll
        for (int ks = 0; ks < KC2 / 8; ks++) {
            wmma::fragment<wmma::matrix_a, 16, 16, 8, wmma::precision::tf32, wmma::row_major> a[4];
#pragma unroll
            for (int i = 0; i < 4; i++)
                wmma::load_matrix_sync(a[i], &As[(wm * 64 + i * 16) * LDP2 + ks * 8], LDP2);
            wmma::fragment<wmma::matrix_b, 16, 16, 8, wmma::precision::tf32, wmma::col_major> b[2];
#pragma unroll
            for (int j = 0; j < 2; j++)
                wmma::load_matrix_sync(b[j], &Bs[(wn * 32 + j * 16) * LDP2 + ks * 8], LDP2);
#pragma unroll
            for (int i = 0; i < 4; i++)
#pragma unroll
                for (int j = 0; j < 2; j++)
                    wmma::mma_sync(acc[i][j], a[i], b[j], acc[i][j]);
        }
        __syncthreads();
    }

    // epilogue: relu + direct wmma store (16-row tiles all-valid or all-OOB)
#pragma unroll
    for (int i = 0; i < 4; i++) {
        const int mrow = m0 + wm * 64 + i * 16;
        if (mrow + 16 > N_NODES) continue;
#pragma unroll
        for (int j = 0; j < 2; j++) {
#pragma unroll
            for (int e = 0; e < acc[i][j].num_elements; e++)
                acc[i][j].x[e] = fmaxf(acc[i][j].x[e], 0.0f);
            wmma::store_matrix_sync(out + (size_t)mrow * DIM_I + n0 + wn * 32 + j * 16,
                                    acc[i][j], DIM_I, wmma::mem_row_major);
        }
    }
}

// ---------------------------------------------------------------------------
extern "C" void kernel_launch(void* const* d_in, const int* in_sizes, int n_in,
                              void* d_out, int out_size) {
    const float* x     = (const float*)d_in[0];
    const int*   eidx  = (const int*)d_in[1];      // int32 (JAX x64 disabled)
    const float* agg_W = (const float*)d_in[2];
    const float* agg_b = (const float*)d_in[3];
    const float* lin_W = (const float*)d_in[4];
    float*       out   = (float*)d_out;

    const int num_edges = in_sizes[1] / 2;
    const int m_blocks = (N_NODES + 127) / 128;         // 782

    cudaFuncSetAttribute(output_gemm_kernel,
                         cudaFuncAttributeMaxDynamicSharedMemorySize, GSMEM_BYTES);

    // 1) per-node transform
    node_transform_kernel<<<m_blocks, 256>>>(x, agg_W, agg_b);
    // 2) zero hn
    zero_hn_kernel<<<6400, 256>>>();
    // 3) scatter-max over edges
    {
        const long long total_threads = (long long)num_edges * 32;
        const int blocks = (int)((total_threads + 255) / 256); // 200000
        scatter_max_kernel<<<blocks, 256>>>(eidx, num_edges);
    }
    // 4) output GEMM + relu  (n-tiles fast; KC2=64, 2-CTA occupancy enforced)
    {
        dim3 grid(DIM_I / 128, m_blocks);               // (8, 782)
        output_gemm_kernel<<<grid, 256, GSMEM_BYTES>>>(x, lin_W, out);
    }
}